// round 13
// baseline (speedup 1.0000x reference)
#include <cuda_runtime.h>
#include <cuda_fp16.h>
#include <cstdint>

#define FF 40
#define DD 768
#define HH 256
#define MAXP 780           // F*(F-1)/2
#define PPAD 832           // 13*64, >= MAXP, multiple of 64
#define BT_TOTAL (64*256)
#define KC 64
#define CHUNK_HALFS 16384  // 256 h-rows x 64 k x fp16 = 32KB, smem-image layout

// ---------------- device scratch (no allocations allowed) ----------------
// g_EWT: chunk-major, pre-swizzled smem image. chunk c, row h, k-unit u(8 halfs):
//   half offset = c*16384 + h*64 + (((kp>>3) ^ (h&7))<<3) + (kp&7),  kp = p & 63
__device__ __align__(128) __half g_EWT[13 * CHUNK_HALFS];
__device__ __align__(16) unsigned long long g_pm[PPAD]; // compacted pair masks
__device__ __align__(16) unsigned long long g_bits[BT_TOTAL];
__device__ __align__(16) float g_scale[BT_TOTAL];
__device__ int g_Pg;

__device__ __forceinline__ uint32_t smem_u32(const void* p) {
    return (uint32_t)__cvta_generic_to_shared(p);
}

__device__ __forceinline__ size_t ewt_off(int h, int p) {
    int c = p >> 6, kp = p & 63;
    return (size_t)c * CHUNK_HALFS + h * 64 + (((kp >> 3) ^ (h & 7)) << 3) + (kp & 7);
}

// closed-form upper-triangular decode: L -> (i, j), base(i) = i*(79-i)/2
__device__ __forceinline__ void pair_decode(int L, int& i, int& j) {
    i = (int)((79.0f - sqrtf((float)(6241 - 8 * L))) * 0.5f);
    while (i * (79 - i) / 2 > L) --i;
    while ((i + 1) * (78 - i) / 2 <= L) ++i;
    j = i + 1 + (L - i * (79 - i) / 2);
}

#define MBARRIER_INIT(a, c) \
    asm volatile("mbarrier.init.shared.b64 [%0], %1;" :: "r"(a), "r"(c) : "memory")
#define MBARRIER_EXPECT_TX(a, b) \
    asm volatile("mbarrier.arrive.expect_tx.shared.b64 _, [%0], %1;" \
                 :: "r"(a), "r"(b) : "memory")
#define MBARRIER_WAIT_PARITY(mbar_addr, phase_parity) do { \
    uint32_t _mbar = (uint32_t)(mbar_addr); \
    uint32_t _par = (uint32_t)(phase_parity); \
    asm volatile( \
        "{\n\t.reg .pred P1;\n\t" \
        "WAIT_LOOP_%=:\n\t" \
        "mbarrier.try_wait.parity.acquire.cta.shared::cta.b64 P1, [%0], %1, 0x989680;\n\t" \
        "@P1 bra.uni WAIT_DONE_%=;\n\t" \
        "bra.uni WAIT_LOOP_%=;\n\t" \
        "WAIT_DONE_%=:\n\t}" \
        :: "r"(_mbar), "r"(_par) : "memory"); \
} while (0)
#define CP_BULK(dst, src, bytes, mb) \
    asm volatile("cp.async.bulk.shared::cluster.global.mbarrier::complete_tx::bytes " \
                 "[%0], [%1], %2, [%3];" \
                 :: "r"(dst), "l"(src), "r"(bytes), "r"(mb) : "memory")

// ---------------- 1) ew_kernel: EWT + pair tables + mask bits/scale ----------------
// grid (104, 8) x 64 threads.
//   ht < 4  : ONE 8p x 64h EW tile
//   ht >= 4 : bits/scale producer, 40 bt-rows per block (416 blocks)
__global__ void __launch_bounds__(64) ew_kernel(const float* __restrict__ E,
                                                const float* __restrict__ W,
                                                const void* __restrict__ avail,
                                                const unsigned int* __restrict__ mask_w) {
    __shared__ __align__(16) float sE[8][36];
    __shared__ __align__(16) float sW[64][36];
    __shared__ __align__(16) unsigned int stage[1600];  // 40 rows x 40 words
    __shared__ unsigned char s_av[FF * FF];
    __shared__ unsigned long long s_avr[FF];
    __shared__ unsigned int s_words[26];
    __shared__ int s_wpre[27];
    __shared__ int s_P;
    __shared__ int s_rb[8];

    int t = threadIdx.x;
    int ht = blockIdx.y;

    // avail dtype: u8 packs random 0/1 bytes -> words outside the valid set
    int okA = 1;
    for (int i = t; i < 400; i += 64) {
        unsigned int v = ((const unsigned int*)avail)[i];
        okA &= (v == 0u) | (v == 1u) | (v == 0x3F800000u);
    }
    okA = __syncthreads_and(okA);
    if (okA) { for (int i = t; i < FF * FF; i += 64) s_av[i] = ((const unsigned int*)avail)[i] != 0u; }
    else     { for (int i = t; i < FF * FF; i += 64) s_av[i] = ((const unsigned char*)avail)[i] != 0; }
    __syncthreads();

    if (t < FF) {
        unsigned long long r = 0ull;
        for (int j = t + 1; j < FF; ++j)
            if (s_av[t * FF + j]) r |= 1ull << j;
        s_avr[t] = r;
    }

    // flags -> 26 ballot words (L = r*64 + t)
    #pragma unroll
    for (int r = 0; r < 13; ++r) {
        int L = r * 64 + t;
        int f = 0;
        if (L < MAXP) {
            int i, j; pair_decode(L, i, j);
            f = s_av[i * FF + j];
        }
        unsigned int bal = __ballot_sync(0xffffffffu, f);
        if ((t & 31) == 0) s_words[r * 2 + (t >> 5)] = bal;
    }
    __syncthreads();
    if (t == 0) {
        int s = 0;
        for (int w = 0; w < 26; ++w) { s_wpre[w] = s; s += __popc(s_words[w]); }
        s_wpre[26] = s; s_P = s;
    }
    __syncthreads();
    int P = s_P;
    int nch64 = (P + 63) >> 6; if (nch64 < 1) nch64 = 1;
    int plim = nch64 * 64;

    // ======== bits/scale producer blocks ========
    if (ht >= 4) {
        int bb = (ht - 4) * 104 + blockIdx.x;       // 0..415
        int row0 = bb * 40;
        if (row0 >= BT_TOTAL) return;
        int nr = BT_TOTAL - row0; if (nr > 40) nr = 40;

        int okM = 1;
        for (int i = t; i < 512; i += 64) {
            unsigned int v = mask_w[i];
            okM &= (v == 0u) | (v == 1u) | (v == 0x3F800000u);
        }
        okM = __syncthreads_and(okM);

        if (okM) {
            for (int idx = t; idx < nr * 40; idx += 64)
                stage[idx] = mask_w[(size_t)row0 * 40 + idx];
        } else {
            for (int idx = t; idx < nr * 10; idx += 64)
                stage[idx] = mask_w[(size_t)row0 * 10 + idx];
        }
        __syncthreads();
        if (t < nr) {
            unsigned long long b = 0ull;
            if (okM) {
                const unsigned int* rp = stage + t * 40;
                #pragma unroll
                for (int f = 0; f < FF; ++f)
                    if (rp[f]) b |= 1ull << f;
            } else {
                const unsigned int* rp = stage + t * 10;
                #pragma unroll
                for (int wi = 0; wi < 10; ++wi) {
                    unsigned int w = rp[wi];
                    #pragma unroll
                    for (int by = 0; by < 4; ++by)
                        if ((w >> (by * 8)) & 0xFFu) b |= 1ull << (wi * 4 + by);
                }
            }
            int cnt = 0;
            unsigned long long x = b;
            while (x) {
                int i = __ffsll((long long)x) - 1;
                x &= x - 1;
                cnt += __popcll(s_avr[i] & b);
            }
            g_bits[row0 + t] = b;
            g_scale[row0 + t] = (cnt > 0) ? (1.0f / (float)cnt) : 0.0f;
        }
        return;
    }

    // block (0,0) publishes pair tables for gemm
    if (blockIdx.x == 0 && ht == 0) {
        if (t == 0) g_Pg = P;
        for (int L = t; L < PPAD; L += 64) {
            if (L < MAXP && ((s_words[L >> 5] >> (L & 31)) & 1u)) {
                int pos = s_wpre[L >> 5] +
                          __popc(s_words[L >> 5] & ((1u << (L & 31)) - 1u));
                int i, j; pair_decode(L, i, j);
                g_pm[pos] = (1ull << i) | (1ull << j);
            }
            if (L >= P) g_pm[L] = ~0ull;
        }
    }

    int p0 = blockIdx.x * 8;
    int h0 = ht * 64;
    if (p0 >= plim) return;                          // never read by gemm
    if (p0 >= P) {                                   // pad rows inside read window
        for (int q = t; q < 8 * 64; q += 64) {       // 8p x 64h halves
            int pq = q & 7, hcz = q >> 3;
            g_EWT[ewt_off(h0 + hcz, p0 + pq)] = __float2half_rn(0.f);
        }
        return;
    }

    if (t < 8) {
        int p = p0 + t;
        int rb = -1;
        if (p < P) {         // find p-th set flag
            int w = 0;
            while (s_wpre[w + 1] <= p) ++w;
            unsigned int word = s_words[w];
            int rem = p - s_wpre[w];
            for (int q = 0; q < rem; ++q) word &= word - 1;
            int L = w * 32 + (__ffs(word) - 1);
            int i, j; pair_decode(L, i, j);
            rb = (i * FF + j) * DD;
        }
        s_rb[t] = rb;
    }
    __syncthreads();

    const int erow = t >> 3, ekq = t & 7;
    const int ebase = s_rb[erow];
    const int prow = (t >> 4) * 2;
    const int hc = t & 15;

    float4 re, rw[8];
    re = make_float4(0.f, 0.f, 0.f, 0.f);
    if (ebase >= 0) re = *(const float4*)(E + ebase + ekq * 4);
    #pragma unroll
    for (int r = 0; r < 8; ++r) {
        int idx = t + 64 * r;
        int row = idx >> 3, kq = idx & 7;
        rw[r] = *(const float4*)(W + (size_t)(h0 + row) * DD + kq * 4);
    }

    float acc[2][4];
    #pragma unroll
    for (int q = 0; q < 2; ++q)
        #pragma unroll
        for (int cc = 0; cc < 4; ++cc) acc[q][cc] = 0.f;

    for (int c = 0; c < DD / 32; ++c) {
        __syncthreads();
        *(float4*)&sE[erow][ekq * 4] = re;
        #pragma unroll
        for (int r = 0; r < 8; ++r) {
            int idx = t + 64 * r;
            int row = idx >> 3, kq = idx & 7;
            *(float4*)&sW[row][kq * 4] = rw[r];
        }
        __syncthreads();
        if (c + 1 < DD / 32) {
            int k0 = (c + 1) * 32;
            re = make_float4(0.f, 0.f, 0.f, 0.f);
            if (ebase >= 0) re = *(const float4*)(E + ebase + k0 + ekq * 4);
            #pragma unroll
            for (int r = 0; r < 8; ++r) {
                int idx = t + 64 * r;
                int row = idx >> 3, kq = idx & 7;
                rw[r] = *(const float4*)(W + (size_t)(h0 + row) * DD + k0 + kq * 4);
            }
        }
        #pragma unroll
        for (int kk = 0; kk < 32; kk += 4) {
            float4 e0 = *(float4*)&sE[prow][kk];
            float4 e1 = *(float4*)&sE[prow + 1][kk];
            #pragma unroll
            for (int cc = 0; cc < 4; ++cc) {
                float4 w0 = *(float4*)&sW[hc + cc * 16][kk];
                acc[0][cc] += e0.x * w0.x + e0.y * w0.y + e0.z * w0.z + e0.w * w0.w;
                acc[1][cc] += e1.x * w0.x + e1.y * w0.y + e1.z * w0.z + e1.w * w0.w;
            }
        }
    }
    #pragma unroll
    for (int q = 0; q < 2; ++q)
        #pragma unroll
        for (int cc = 0; cc < 4; ++cc)
            g_EWT[ewt_off(h0 + hc + cc * 16, p0 + prow + q)] = __float2half_rn(acc[q][cc]);
}

// ---------------- 2) mma.sync GEMM: out = (sel @ EW) * (1/cnt) + bias ----------------
// BM=64, BN=256, KC=64; 256 threads = 8 warps as 2m x 4n, warp tile 32m x 64n.
// B via cp.async.bulk (2 x 16KB per chunk) + mbarrier; pure-load prologue.
#define ABYTES 8192                  // 64 x 64 fp16
#define BBYTES 32768                 // 256 x 64 fp16 (smem image == gmem chunk)
#define BUFB (ABYTES + BBYTES)       // 40 KB
#define DSMEM_BYTES (2 * BUFB + 128)

#define LDSM4(r0, r1, r2, r3, addr) \
    asm volatile("ldmatrix.sync.aligned.m8n8.x4.shared.b16 {%0,%1,%2,%3}, [%4];" \
                 : "=r"(r0), "=r"(r1), "=r"(r2), "=r"(r3) : "r"(addr))

#define MMA_F16(d, a, b0v, b1v) \
    asm volatile("mma.sync.aligned.m16n8k16.row.col.f32.f16.f16.f32 " \
                 "{%0,%1,%2,%3}, {%4,%5,%6,%7}, {%8,%9}, {%0,%1,%2,%3};" \
                 : "+f"((d)[0]), "+f"((d)[1]), "+f"((d)[2]), "+f"((d)[3]) \
                 : "r"((a)[0]), "r"((a)[1]), "r"((a)[2]), "r"((a)[3]), \
                   "r"(b0v), "r"(b1v))

__global__ void __launch_bounds__(256)
gemm_kernel(const float* __restrict__ bias, float* __restrict__ out) {
    extern __shared__ char dyn_raw[];
    __shared__ __align__(16) unsigned long long s_pm[PPAD];
    __shared__ __align__(16) unsigned long long s_bits[64];
    __shared__ __align__(16) float s_scale[64];
    __shared__ __align__(16) float s_bias[HH];
    __shared__ __align__(8) unsigned long long s_mbar[2];

    uint32_t raw = smem_u32(dyn_raw);
    uint32_t base = (raw + 127u) & ~127u;

    const int t = threadIdx.x;
    const int lane = t & 31, wid = t >> 5;
    const int wm = (wid & 1) * 32;      // 2 m-groups of 32 rows
    const int wn = (wid >> 1) * 64;     // 4 n-groups of 64 cols
    const int m0 = blockIdx.x * 64;
    const uint32_t mbar0 = smem_u32(&s_mbar[0]);

    // ---- B chunk: 2 x 16KB bulk copies into smem image ----
    #define ISSUE_BULK(c, b) do {                                                  \
        if (t == 0) {                                                              \
            uint32_t mb = mbar0 + (b) * 8;                                         \
            MBARRIER_EXPECT_TX(mb, 32768u);                                        \
            uint32_t dst = base + (b) * BUFB + ABYTES;                             \
            const char* src = (const char*)g_EWT + (size_t)(c) * 32768;            \
            CP_BULK(dst, src, 16384u, mb);                                         \
            CP_BULK(dst + 16384u, src + 16384, 16384u, mb);                        \
        }                                                                          \
    } while (0)

    #define BUILD_A(c, bufbase) do {                                               \
        _Pragma("unroll")                                                          \
        for (int r = 0; r < 2; ++r) {                                              \
            int idx = t + r * 256;                                                 \
            int m = idx >> 3, kc = idx & 7;                                        \
            unsigned long long bb = s_bits[m];                                     \
            int pb = (c) * KC + kc * 8;                                            \
            unsigned long long q0 = s_pm[pb+0], q1 = s_pm[pb+1];                   \
            unsigned long long q2 = s_pm[pb+2], q3 = s_pm[pb+3];                   \
            unsigned long long q4 = s_pm[pb+4], q5 = s_pm[pb+5];                   \
            unsigned long long q6 = s_pm[pb+6], q7 = s_pm[pb+7];                   \
            uint32_t w0 = (((bb & q0) == q0) ? 0x3C00u : 0u) |                     \
                          (((bb & q1) == q1) ? 0x3C000000u : 0u);                  \
            uint32_t w1 = (((bb & q2) == q2) ? 0x3C00u : 0u) |                     \
                          (((bb & q3) == q3) ? 0x3C000000u : 0u);                  \
            uint32_t w2 = (((bb & q4) == q4) ? 0x3C00u : 0u) |                     \
                          (((bb & q5) == q5) ? 0x3C000000u : 0u);                  \
            uint32_t w3 = (((bb & q6) == q6) ? 0x3C00u : 0u) |                     \
                          (((bb & q7) == q7) ? 0x3C000000u : 0u);                  \
            uint32_t dst = (bufbase) + m * 128 + ((kc ^ (m & 7)) << 4);            \
            asm volatile("st.shared.v4.b32 [%0], {%1,%2,%3,%4};"                   \
                         :: "r"(dst), "r"(w0), "r"(w1), "r"(w2), "r"(w3));         \
        }                                                                          \
    } while (0)

    if (t == 0) {
        MBARRIER_INIT(mbar0, 1);
        MBARRIER_INIT(mbar0 + 8, 1);
    }
    __syncthreads();                     // init visible before expect/complete
    ISSUE_BULK(0, 0);

    // ---- prologue: pure loads ----
    int P = g_Pg;
    int nch = (P + KC - 1) / KC; if (nch < 1) nch = 1;
    for (int i = t; i < PPAD; i += 256) s_pm[i] = g_pm[i];
    if (t < 64) { s_bits[t] = g_bits[m0 + t]; s_scale[t] = g_scale[m0 + t]; }
    if (t < HH) s_bias[t] = bias[t];
    __syncthreads();
    BUILD_A(0, base);
    __syncthreads();

    float acc[2][8][4];
    #pragma unroll
    for (int i = 0; i < 2; ++i)
        #pragma unroll
        for (int j = 0; j < 8; ++j)
            #pragma unroll
            for (int q = 0; q < 4; ++q) acc[i][j][q] = 0.f;

    for (int c = 0; c < nch; ++c) {
        int b = c & 1;
        uint32_t cur = base + b * BUFB;
        MBARRIER_WAIT_PARITY(mbar0 + b * 8, (c >> 1) & 1);

        uint32_t Ab = cur, Bb = cur + ABYTES;
        #pragma unroll
        for (int ks = 0; ks < 4; ++ks) {
            uint32_t a[2][4];
            #pragma unroll
            for (int mi = 0; mi < 2; ++mi) {
                int arow = wm + mi * 16 + (lane & 7) + ((lane >> 3) & 1) * 8;
                int akc = ks * 2 + (lane >> 4);
                uint32_t ad = Ab + arow * 128 + ((akc ^ (arow & 7)) << 4);
                LDSM4(a[mi][0], a[mi][1], a[mi][2], a[mi][3], ad);
            }
            #pragma unroll
            for (int nb2 = 0; nb2 < 4; ++nb2) {
                int brow = wn + nb2 * 16 + (lane & 7) + (lane >> 4) * 8;
                int bkc = ks * 2 + ((lane >> 3) & 1);
                uint32_t off = brow * 128 + ((bkc ^ (brow & 7)) << 4);
                uint32_t b0, b1, b2, b3;
                LDSM4(b0, b1, b2, b3, Bb + off);
                #pragma unroll
                for (int mi = 0; mi < 2; ++mi) {
                    MMA_F16(acc[mi][nb2 * 2 + 0], a[mi], b0, b1);
                    MMA_F16(acc[mi][nb2 * 2 + 1], a[mi], b2, b3);
                }
            }
        }
        __syncthreads();                 // all warps done with buffer b
        if (c + 1 < nch) {
            ISSUE_BULK(c + 1, (c + 1) & 1);
            BUILD_A(c + 1, base + ((c + 1) & 1) * BUFB);
            __syncthreads();             // A(c+1) visible
        }
    }

    // ---- epilogue: scale by 1/cnt, add bias, store ----
    #pragma unroll
    for (int mi = 0; mi < 2; ++mi) {
        int rl = wm + mi * 16 + (lane >> 2);
        int row0 = m0 + rl;
        float sc0 = s_scale[rl];
        float sc1 = s_scale[rl + 8];
        #pragma unroll
        for (int nf = 0; nf < 8; ++nf) {
            int col = wn + (nf >> 1) * 16 + (nf & 1) * 8 + 2 * (lane & 3);
            float bv0 = s_bias[col], bv1 = s_bias[col + 1];
            float2 o0, o1;
            o0.x = acc[mi][nf][0] * sc0 + bv0;
            o0.y = acc[mi][nf][1] * sc0 + bv1;
            o1.x = acc[mi][nf][2] * sc1 + bv0;
            o1.y = acc[mi][nf][3] * sc1 + bv1;
            *(float2*)(out + (size_t)row0 * HH + col) = o0;
            *(float2*)(out + (size_t)(row0 + 8) * HH + col) = o1;
        }
    }
}

// ---------------- launch ----------------
extern "C" void kernel_launch(void* const* d_in, const int* in_sizes, int n_in,
                              void* d_out, int out_size) {
    const void* mask = d_in[0];                    // [64,256,40] bool
    const float* E = (const float*)d_in[1];        // [40,40,768] f32
    const void* avail = (const void*)d_in[2];      // [40,40] bool
    const float* W = (const float*)d_in[3];        // [256,768] f32
    const float* bias = (const float*)d_in[4];     // [256] f32
    float* out = (float*)d_out;                    // [64,256,256] f32

    cudaFuncSetAttribute(gemm_kernel, cudaFuncAttributeMaxDynamicSharedMemorySize,
                         DSMEM_BYTES);

    ew_kernel<<<dim3(104, 8), 64>>>(E, W, avail, (const unsigned int*)mask);
    gemm_kernel<<<BT_TOTAL / 64, 256, DSMEM_BYTES>>>(bias, out);
}

// round 14
// speedup vs baseline: 1.0345x; 1.0345x over previous
#include <cuda_runtime.h>
#include <cuda_fp16.h>
#include <cstdint>

#define FF 40
#define DD 768
#define HH 256
#define MAXP 780           // F*(F-1)/2
#define PPAD 832           // 13*64, >= MAXP, multiple of 64
#define BT_TOTAL (64*256)
#define KC 64
#define CHUNK_HALFS 16384  // 256 h-rows x 64 k x fp16 = 32KB, smem-image layout

// ---------------- device scratch (no allocations allowed) ----------------
// g_EWT: chunk-major, pre-swizzled smem image. chunk c, row h, k pos kp (p&63):
//   half offset = c*16384 + h*64 + (((kp>>3) ^ (h&7))<<3) + (kp&7)
__device__ __align__(128) __half g_EWT[13 * CHUNK_HALFS];
__device__ __align__(16) unsigned long long g_pm[PPAD]; // compacted pair masks
__device__ __align__(16) unsigned long long g_bits[BT_TOTAL];
__device__ __align__(16) float g_scale[BT_TOTAL];
__device__ int g_Pg;

__device__ __forceinline__ uint32_t smem_u32(const void* p) {
    return (uint32_t)__cvta_generic_to_shared(p);
}

__device__ __forceinline__ size_t ewt_off(int h, int p) {
    int c = p >> 6, kp = p & 63;
    return (size_t)c * CHUNK_HALFS + h * 64 + (((kp >> 3) ^ (h & 7)) << 3) + (kp & 7);
}

// closed-form upper-triangular decode: L -> (i, j), base(i) = i*(79-i)/2
__device__ __forceinline__ void pair_decode(int L, int& i, int& j) {
    i = (int)((79.0f - sqrtf((float)(6241 - 8 * L))) * 0.5f);
    while (i * (79 - i) / 2 > L) --i;
    while ((i + 1) * (78 - i) / 2 <= L) ++i;
    j = i + 1 + (L - i * (79 - i) / 2);
}

#define MBARRIER_INIT(a, c) \
    asm volatile("mbarrier.init.shared.b64 [%0], %1;" :: "r"(a), "r"(c) : "memory")
#define MBARRIER_EXPECT_TX(a, b) \
    asm volatile("mbarrier.arrive.expect_tx.shared.b64 _, [%0], %1;" \
                 :: "r"(a), "r"(b) : "memory")
#define MBARRIER_WAIT_PARITY(mbar_addr, phase_parity) do { \
    uint32_t _mbar = (uint32_t)(mbar_addr); \
    uint32_t _par = (uint32_t)(phase_parity); \
    asm volatile( \
        "{\n\t.reg .pred P1;\n\t" \
        "WAIT_LOOP_%=:\n\t" \
        "mbarrier.try_wait.parity.acquire.cta.shared::cta.b64 P1, [%0], %1, 0x989680;\n\t" \
        "@P1 bra.uni WAIT_DONE_%=;\n\t" \
        "bra.uni WAIT_LOOP_%=;\n\t" \
        "WAIT_DONE_%=:\n\t}" \
        :: "r"(_mbar), "r"(_par) : "memory"); \
} while (0)
#define CP_BULK(dst, src, bytes, mb) \
    asm volatile("cp.async.bulk.shared::cluster.global.mbarrier::complete_tx::bytes " \
                 "[%0], [%1], %2, [%3];" \
                 :: "r"(dst), "l"(src), "r"(bytes), "r"(mb) : "memory")

// ---------------- 1) ew_kernel: EWT + pair tables + mask bits/scale ----------------
// grid (52, 8) x 128 threads.
//   ht < 4  : ONE 16p x 64h EW tile, K-chunks of 64
//   ht >= 4 : bits/scale producer, 79 bt-rows per block (208 blocks)
__global__ void __launch_bounds__(128) ew_kernel(const float* __restrict__ E,
                                                 const float* __restrict__ W,
                                                 const void* __restrict__ avail,
                                                 const unsigned int* __restrict__ mask_w) {
    __shared__ __align__(16) float sE[16][68];   // 272B pitch, 16B-aligned rows
    __shared__ __align__(16) float sW[64][68];
    __shared__ __align__(16) unsigned int stage[79 * 40];
    __shared__ unsigned char s_av[FF * FF];
    __shared__ unsigned long long s_avr[FF];
    __shared__ unsigned int s_words[25];
    __shared__ int s_wpre[26];
    __shared__ int s_P;
    __shared__ int s_rb[16];

    int t = threadIdx.x;
    int ht = blockIdx.y;

    // avail dtype: u8 packs random 0/1 bytes -> words outside the valid set
    int okA = 1;
    for (int i = t; i < 400; i += 128) {
        unsigned int v = ((const unsigned int*)avail)[i];
        okA &= (v == 0u) | (v == 1u) | (v == 0x3F800000u);
    }
    okA = __syncthreads_and(okA);
    if (okA) { for (int i = t; i < FF * FF; i += 128) s_av[i] = ((const unsigned int*)avail)[i] != 0u; }
    else     { for (int i = t; i < FF * FF; i += 128) s_av[i] = ((const unsigned char*)avail)[i] != 0; }
    __syncthreads();

    if (t < FF) {
        unsigned long long r = 0ull;
        for (int j = t + 1; j < FF; ++j)
            if (s_av[t * FF + j]) r |= 1ull << j;
        s_avr[t] = r;
    }

    // flags -> 25 ballot words (L = r*128 + t)
    #pragma unroll
    for (int r = 0; r < 7; ++r) {
        int L = r * 128 + t;
        int f = 0;
        if (L < MAXP) {
            int i, j; pair_decode(L, i, j);
            f = s_av[i * FF + j];
        }
        unsigned int bal = __ballot_sync(0xffffffffu, f);
        if ((t & 31) == 0) {
            int wi = r * 4 + (t >> 5);
            if (wi < 25) s_words[wi] = bal;
        }
    }
    __syncthreads();
    if (t == 0) {
        int s = 0;
        for (int w = 0; w < 25; ++w) { s_wpre[w] = s; s += __popc(s_words[w]); }
        s_wpre[25] = s; s_P = s;
    }
    __syncthreads();
    int P = s_P;
    int nch64 = (P + 63) >> 6; if (nch64 < 1) nch64 = 1;
    int plim = nch64 * 64;

    // ======== bits/scale producer blocks ========
    if (ht >= 4) {
        int bb = (ht - 4) * 52 + blockIdx.x;        // 0..207
        int row0 = bb * 79;
        if (row0 >= BT_TOTAL) return;
        int nr = BT_TOTAL - row0; if (nr > 79) nr = 79;

        int okM = 1;
        for (int i = t; i < 512; i += 128) {
            unsigned int v = mask_w[i];
            okM &= (v == 0u) | (v == 1u) | (v == 0x3F800000u);
        }
        okM = __syncthreads_and(okM);

        if (okM) {
            for (int idx = t; idx < nr * 40; idx += 128)
                stage[idx] = mask_w[(size_t)row0 * 40 + idx];
        } else {
            for (int idx = t; idx < nr * 10; idx += 128)
                stage[idx] = mask_w[(size_t)row0 * 10 + idx];
        }
        __syncthreads();
        if (t < nr) {
            unsigned long long b = 0ull;
            if (okM) {
                const unsigned int* rp = stage + t * 40;
                #pragma unroll
                for (int f = 0; f < FF; ++f)
                    if (rp[f]) b |= 1ull << f;
            } else {
                const unsigned int* rp = stage + t * 10;
                #pragma unroll
                for (int wi = 0; wi < 10; ++wi) {
                    unsigned int w = rp[wi];
                    #pragma unroll
                    for (int by = 0; by < 4; ++by)
                        if ((w >> (by * 8)) & 0xFFu) b |= 1ull << (wi * 4 + by);
                }
            }
            int cnt = 0;
            unsigned long long x = b;
            while (x) {
                int i = __ffsll((long long)x) - 1;
                x &= x - 1;
                cnt += __popcll(s_avr[i] & b);
            }
            g_bits[row0 + t] = b;
            g_scale[row0 + t] = (cnt > 0) ? (1.0f / (float)cnt) : 0.0f;
        }
        return;
    }

    // block (0,0) publishes pair tables for gemm
    if (blockIdx.x == 0 && ht == 0) {
        if (t == 0) g_Pg = P;
        for (int L = t; L < PPAD; L += 128) {
            if (L < MAXP && ((s_words[L >> 5] >> (L & 31)) & 1u)) {
                int pos = s_wpre[L >> 5] +
                          __popc(s_words[L >> 5] & ((1u << (L & 31)) - 1u));
                int i, j; pair_decode(L, i, j);
                g_pm[pos] = (1ull << i) | (1ull << j);
            }
            if (L >= P) g_pm[L] = ~0ull;
        }
    }

    int p0 = blockIdx.x * 16;
    int h0 = ht * 64;
    if (p0 >= plim) return;                          // never read by gemm
    if (p0 >= P) {                                   // pad rows inside read window
        for (int q = t; q < 16 * 64; q += 128) {     // 16p x 64h halves
            int pq = q & 15, hcz = q >> 4;
            g_EWT[ewt_off(h0 + hcz, p0 + pq)] = __float2half_rn(0.f);
        }
        return;
    }

    if (t < 16) {
        int p = p0 + t;
        int rb = -1;
        if (p < P) {         // find p-th set flag
            int w = 0;
            while (s_wpre[w + 1] <= p) ++w;
            unsigned int word = s_words[w];
            int rem = p - s_wpre[w];
            for (int q = 0; q < rem; ++q) word &= word - 1;
            int L = w * 32 + (__ffs(word) - 1);
            int i, j; pair_decode(L, i, j);
            rb = (i * FF + j) * DD;
        }
        s_rb[t] = rb;
    }
    __syncthreads();

    const int erow = t >> 4, ekq0 = (t & 15);        // E: 2 rows/thread slots below
    const int prow = (t >> 4) * 2;                   // 8 groups x 2p = 16p
    const int hc = t & 15;                           // 4 h cols: hc + cc*16

    // prefetch regs: E 2 float4, W 8 float4
    float4 re[2], rw[8];
    #pragma unroll
    for (int r = 0; r < 2; ++r) {
        int idx = t + r * 128;                       // 256 slots: 16 rows x 16 kq
        int row = idx >> 4, kq = idx & 15;
        int b = s_rb[row];
        re[r] = make_float4(0.f, 0.f, 0.f, 0.f);
        if (b >= 0) re[r] = *(const float4*)(E + b + kq * 4);
    }
    #pragma unroll
    for (int r = 0; r < 8; ++r) {
        int idx = t + r * 128;                       // 1024 slots: 64 rows x 16 kq
        int row = idx >> 4, kq = idx & 15;
        rw[r] = *(const float4*)(W + (size_t)(h0 + row) * DD + kq * 4);
    }
    (void)erow; (void)ekq0;

    float acc[2][4];
    #pragma unroll
    for (int q = 0; q < 2; ++q)
        #pragma unroll
        for (int cc = 0; cc < 4; ++cc) acc[q][cc] = 0.f;

    for (int c = 0; c < DD / 64; ++c) {              // 12 chunks of K=64
        __syncthreads();
        #pragma unroll
        for (int r = 0; r < 2; ++r) {
            int idx = t + r * 128;
            int row = idx >> 4, kq = idx & 15;
            *(float4*)&sE[row][kq * 4] = re[r];
        }
        #pragma unroll
        for (int r = 0; r < 8; ++r) {
            int idx = t + r * 128;
            int row = idx >> 4, kq = idx & 15;
            *(float4*)&sW[row][kq * 4] = rw[r];
        }
        __syncthreads();
        if (c + 1 < DD / 64) {
            int k0 = (c + 1) * 64;
            #pragma unroll
            for (int r = 0; r < 2; ++r) {
                int idx = t + r * 128;
                int row = idx >> 4, kq = idx & 15;
                int b = s_rb[row];
                re[r] = make_float4(0.f, 0.f, 0.f, 0.f);
                if (b >= 0) re[r] = *(const float4*)(E + b + k0 + kq * 4);
            }
            #pragma unroll
            for (int r = 0; r < 8; ++r) {
                int idx = t + r * 128;
                int row = idx >> 4, kq = idx & 15;
                rw[r] = *(const float4*)(W + (size_t)(h0 + row) * DD + k0 + kq * 4);
            }
        }
        #pragma unroll
        for (int kk = 0; kk < 64; kk += 4) {
            float4 e0 = *(float4*)&sE[prow][kk];
            float4 e1 = *(float4*)&sE[prow + 1][kk];
            #pragma unroll
            for (int cc = 0; cc < 4; ++cc) {
                float4 w0 = *(float4*)&sW[hc + cc * 16][kk];
                acc[0][cc] += e0.x * w0.x + e0.y * w0.y + e0.z * w0.z + e0.w * w0.w;
                acc[1][cc] += e1.x * w0.x + e1.y * w0.y + e1.z * w0.z + e1.w * w0.w;
            }
        }
    }
    #pragma unroll
    for (int q = 0; q < 2; ++q)
        #pragma unroll
        for (int cc = 0; cc < 4; ++cc)
            g_EWT[ewt_off(h0 + hc + cc * 16, p0 + prow + q)] = __float2half_rn(acc[q][cc]);
}

// ---------------- 2) mma.sync GEMM: out = (sel @ EW) * (1/cnt) + bias ----------------
// BM=64, BN=256, KC=64; 256 threads = 8 warps as 2m x 4n, warp tile 32m x 64n.
// B via cp.async.bulk issued ONE CHUNK AHEAD (latency hidden under compute).
#define ABYTES 8192                  // 64 x 64 fp16
#define BBYTES 32768                 // 256 x 64 fp16 (smem image == gmem chunk)
#define BUFB (ABYTES + BBYTES)       // 40 KB
#define DSMEM_BYTES (2 * BUFB + 128)

#define LDSM4(r0, r1, r2, r3, addr) \
    asm volatile("ldmatrix.sync.aligned.m8n8.x4.shared.b16 {%0,%1,%2,%3}, [%4];" \
                 : "=r"(r0), "=r"(r1), "=r"(r2), "=r"(r3) : "r"(addr))

#define MMA_F16(d, a, b0v, b1v) \
    asm volatile("mma.sync.aligned.m16n8k16.row.col.f32.f16.f16.f32 " \
                 "{%0,%1,%2,%3}, {%4,%5,%6,%7}, {%8,%9}, {%0,%1,%2,%3};" \
                 : "+f"((d)[0]), "+f"((d)[1]), "+f"((d)[2]), "+f"((d)[3]) \
                 : "r"((a)[0]), "r"((a)[1]), "r"((a)[2]), "r"((a)[3]), \
                   "r"(b0v), "r"(b1v))

__global__ void __launch_bounds__(256)
gemm_kernel(const float* __restrict__ bias, float* __restrict__ out) {
    extern __shared__ char dyn_raw[];
    __shared__ __align__(16) unsigned long long s_pm[PPAD];
    __shared__ __align__(16) unsigned long long s_bits[64];
    __shared__ __align__(16) float s_scale[64];
    __shared__ __align__(16) float s_bias[HH];
    __shared__ __align__(8) unsigned long long s_mbar[2];

    uint32_t raw = smem_u32(dyn_raw);
    uint32_t base = (raw + 127u) & ~127u;

    const int t = threadIdx.x;
    const int lane = t & 31, wid = t >> 5;
    const int wm = (wid & 1) * 32;      // 2 m-groups of 32 rows
    const int wn = (wid >> 1) * 64;     // 4 n-groups of 64 cols
    const int m0 = blockIdx.x * 64;
    const uint32_t mbar0 = smem_u32(&s_mbar[0]);

    #define ISSUE_BULK(c, b) do {                                                  \
        if (t == 0) {                                                              \
            uint32_t mb = mbar0 + (b) * 8;                                         \
            MBARRIER_EXPECT_TX(mb, 32768u);                                        \
            uint32_t dst = base + (b) * BUFB + ABYTES;                             \
            const char* src = (const char*)g_EWT + (size_t)(c) * 32768;            \
            CP_BULK(dst, src, 16384u, mb);                                         \
            CP_BULK(dst + 16384u, src + 16384, 16384u, mb);                        \
        }                                                                          \
    } while (0)

    #define BUILD_A(c, bufbase) do {                                               \
        _Pragma("unroll")                                                          \
        for (int r = 0; r < 2; ++r) {                                              \
            int idx = t + r * 256;                                                 \
            int m = idx >> 3, kc = idx & 7;                                        \
            unsigned long long bb = s_bits[m];                                     \
            int pb = (c) * KC + kc * 8;                                            \
            unsigned long long q0 = s_pm[pb+0], q1 = s_pm[pb+1];                   \
            unsigned long long q2 = s_pm[pb+2], q3 = s_pm[pb+3];                   \
            unsigned long long q4 = s_pm[pb+4], q5 = s_pm[pb+5];                   \
            unsigned long long q6 = s_pm[pb+6], q7 = s_pm[pb+7];                   \
            uint32_t w0 = (((bb & q0) == q0) ? 0x3C00u : 0u) |                     \
                          (((bb & q1) == q1) ? 0x3C000000u : 0u);                  \
            uint32_t w1 = (((bb & q2) == q2) ? 0x3C00u : 0u) |                     \
                          (((bb & q3) == q3) ? 0x3C000000u : 0u);                  \
            uint32_t w2 = (((bb & q4) == q4) ? 0x3C00u : 0u) |                     \
                          (((bb & q5) == q5) ? 0x3C000000u : 0u);                  \
            uint32_t w3 = (((bb & q6) == q6) ? 0x3C00u : 0u) |                     \
                          (((bb & q7) == q7) ? 0x3C000000u : 0u);                  \
            uint32_t dst = (bufbase) + m * 128 + ((kc ^ (m & 7)) << 4);            \
            asm volatile("st.shared.v4.b32 [%0], {%1,%2,%3,%4};"                   \
                         :: "r"(dst), "r"(w0), "r"(w1), "r"(w2), "r"(w3));         \
        }                                                                          \
    } while (0)

    if (t == 0) {
        MBARRIER_INIT(mbar0, 1);
        MBARRIER_INIT(mbar0 + 8, 1);
    }
    __syncthreads();                     // init visible before expect/complete
    ISSUE_BULK(0, 0);

    // ---- prologue: pure loads ----
    int P = g_Pg;
    int nch = (P + KC - 1) / KC; if (nch < 1) nch = 1;
    for (int i = t; i < PPAD; i += 256) s_pm[i] = g_pm[i];
    if (t < 64) { s_bits[t] = g_bits[m0 + t]; s_scale[t] = g_scale[m0 + t]; }
    if (t < HH) s_bias[t] = bias[t];
    __syncthreads();
    BUILD_A(0, base);
    __syncthreads();

    float acc[2][8][4];
    #pragma unroll
    for (int i = 0; i < 2; ++i)
        #pragma unroll
        for (int j = 0; j < 8; ++j)
            #pragma unroll
            for (int q = 0; q < 4; ++q) acc[i][j][q] = 0.f;

    for (int c = 0; c < nch; ++c) {
        int b = c & 1;
        uint32_t cur = base + b * BUFB;
        // prefetch chunk c+1 into the other buffer (free since chunk c-1 ended)
        if (c + 1 < nch) {
            ISSUE_BULK(c + 1, (c + 1) & 1);
            BUILD_A(c + 1, base + ((c + 1) & 1) * BUFB);
        }
        MBARRIER_WAIT_PARITY(mbar0 + b * 8, (c >> 1) & 1);

        uint32_t Ab = cur, Bb = cur + ABYTES;
        #pragma unroll
        for (int ks = 0; ks < 4; ++ks) {
            uint32_t a[2][4];
            #pragma unroll
            for (int mi = 0; mi < 2; ++mi) {
                int arow = wm + mi * 16 + (lane & 7) + ((lane >> 3) & 1) * 8;
                int akc = ks * 2 + (lane >> 4);
                uint32_t ad = Ab + arow * 128 + ((akc ^ (arow & 7)) << 4);
                LDSM4(a[mi][0], a[mi][1], a[mi][2], a[mi][3], ad);
            }
            #pragma unroll
            for (int nb2 = 0; nb2 < 4; ++nb2) {
                int brow = wn + nb2 * 16 + (lane & 7) + (lane >> 4) * 8;
                int bkc = ks * 2 + ((lane >> 3) & 1);
                uint32_t off = brow * 128 + ((bkc ^ (brow & 7)) << 4);
                uint32_t b0, b1, b2, b3;
                LDSM4(b0, b1, b2, b3, Bb + off);
                #pragma unroll
                for (int mi = 0; mi < 2; ++mi) {
                    MMA_F16(acc[mi][nb2 * 2 + 0], a[mi], b0, b1);
                    MMA_F16(acc[mi][nb2 * 2 + 1], a[mi], b2, b3);
                }
            }
        }
        __syncthreads();   // delimit buffer reuse; makes BUILD_A(c+1) visible
    }

    // ---- epilogue: scale by 1/cnt, add bias, store ----
    #pragma unroll
    for (int mi = 0; mi < 2; ++mi) {
        int rl = wm + mi * 16 + (lane >> 2);
        int row0 = m0 + rl;
        float sc0 = s_scale[rl];
        float sc1 = s_scale[rl + 8];
        #pragma unroll
        for (int nf = 0; nf < 8; ++nf) {
            int col = wn + (nf >> 1) * 16 + (nf & 1) * 8 + 2 * (lane & 3);
            float bv0 = s_bias[col], bv1 = s_bias[col + 1];
            float2 o0, o1;
            o0.x = acc[mi][nf][0] * sc0 + bv0;
            o0.y = acc[mi][nf][1] * sc0 + bv1;
            o1.x = acc[mi][nf][2] * sc1 + bv0;
            o1.y = acc[mi][nf][3] * sc1 + bv1;
            *(float2*)(out + (size_t)row0 * HH + col) = o0;
            *(float2*)(out + (size_t)(row0 + 8) * HH + col) = o1;
        }
    }
}

// ---------------- launch ----------------
extern "C" void kernel_launch(void* const* d_in, const int* in_sizes, int n_in,
                              void* d_out, int out_size) {
    const void* mask = d_in[0];                    // [64,256,40] bool
    const float* E = (const float*)d_in[1];        // [40,40,768] f32
    const void* avail = (const void*)d_in[2];      // [40,40] bool
    const float* W = (const float*)d_in[3];        // [256,768] f32
    const float* bias = (const float*)d_in[4];     // [256] f32
    float* out = (float*)d_out;                    // [64,256,256] f32

    cudaFuncSetAttribute(gemm_kernel, cudaFuncAttributeMaxDynamicSharedMemorySize,
                         DSMEM_BYTES);

    ew_kernel<<<dim3(52, 8), 128>>>(E, W, avail, (const unsigned int*)mask);
    gemm_kernel<<<BT_TOTAL / 64, 256, DSMEM_BYTES>>>(bias, out);
}

// round 15
// speedup vs baseline: 1.1284x; 1.0907x over previous
#include <cuda_runtime.h>
#include <cuda_fp16.h>
#include <cstdint>

#define FF 40
#define DD 768
#define HH 256
#define MAXP 780           // F*(F-1)/2
#define PPAD 832           // 13*64
#define BT_TOTAL (64*256)
#define KC 64
#define CHUNK_HALFS 16384  // 256 h-rows x 64 k x fp16 = 32KB, smem-image layout
#define NCTA 256

// ---------------- device scratch (no allocations allowed) ----------------
// g_EWT: chunk-major, pre-swizzled smem image. chunk c, row h, k pos kp (p&63):
//   half offset = c*16384 + h*64 + (((kp>>3) ^ (h&7))<<3) + (kp&7)
__device__ __align__(128) __half g_EWT[13 * CHUNK_HALFS];
__device__ unsigned int g_bar;     // monotonic grid barrier (never reset)

__device__ __forceinline__ uint32_t smem_u32(const void* p) {
    return (uint32_t)__cvta_generic_to_shared(p);
}

__device__ __forceinline__ size_t ewt_off(int h, int p) {
    int c = p >> 6, kp = p & 63;
    return (size_t)c * CHUNK_HALFS + h * 64 + (((kp >> 3) ^ (h & 7)) << 3) + (kp & 7);
}

// closed-form upper-triangular decode: L -> (i, j), base(i) = i*(79-i)/2
__device__ __forceinline__ void pair_decode(int L, int& i, int& j) {
    i = (int)((79.0f - sqrtf((float)(6241 - 8 * L))) * 0.5f);
    while (i * (79 - i) / 2 > L) --i;
    while ((i + 1) * (78 - i) / 2 <= L) ++i;
    j = i + 1 + (L - i * (79 - i) / 2);
}

#define MBARRIER_INIT(a, c) \
    asm volatile("mbarrier.init.shared.b64 [%0], %1;" :: "r"(a), "r"(c) : "memory")
#define MBARRIER_EXPECT_TX(a, b) \
    asm volatile("mbarrier.arrive.expect_tx.shared.b64 _, [%0], %1;" \
                 :: "r"(a), "r"(b) : "memory")
#define MBARRIER_WAIT_PARITY(mbar_addr, phase_parity) do { \
    uint32_t _mbar = (uint32_t)(mbar_addr); \
    uint32_t _par = (uint32_t)(phase_parity); \
    asm volatile( \
        "{\n\t.reg .pred P1;\n\t" \
        "WAIT_LOOP_%=:\n\t" \
        "mbarrier.try_wait.parity.acquire.cta.shared::cta.b64 P1, [%0], %1, 0x989680;\n\t" \
        "@P1 bra.uni WAIT_DONE_%=;\n\t" \
        "bra.uni WAIT_LOOP_%=;\n\t" \
        "WAIT_DONE_%=:\n\t}" \
        :: "r"(_mbar), "r"(_par) : "memory"); \
} while (0)
#define CP_BULK(dst, src, bytes, mb) \
    asm volatile("cp.async.bulk.shared::cluster.global.mbarrier::complete_tx::bytes " \
                 "[%0], [%1], %2, [%3];" \
                 :: "r"(dst), "l"(src), "r"(bytes), "r"(mb) : "memory")

#define LDSM4(r0, r1, r2, r3, addr) \
    asm volatile("ldmatrix.sync.aligned.m8n8.x4.shared.b16 {%0,%1,%2,%3}, [%4];" \
                 : "=r"(r0), "=r"(r1), "=r"(r2), "=r"(r3) : "r"(addr))

#define MMA_F16(d, a, b0v, b1v) \
    asm volatile("mma.sync.aligned.m16n8k16.row.col.f32.f16.f16.f32 " \
                 "{%0,%1,%2,%3}, {%4,%5,%6,%7}, {%8,%9}, {%0,%1,%2,%3};" \
                 : "+f"((d)[0]), "+f"((d)[1]), "+f"((d)[2]), "+f"((d)[3]) \
                 : "r"((a)[0]), "r"((a)[1]), "r"((a)[2]), "r"((a)[3]), \
                   "r"(b0v), "r"(b1v))

#define ABYTES 8192                  // 64 x 64 fp16
#define BBYTES 32768                 // 256 x 64 fp16 (smem image == gmem chunk)
#define BUFB (ABYTES + BBYTES)       // 40 KB
#define DSMEM_BYTES (2 * BUFB + 128)

// ==================== fused kernel: grid 256 x 256 thr, 1 wave ====================
__global__ void __launch_bounds__(256, 2)
fused_kernel(const float* __restrict__ E, const float* __restrict__ W,
             const void* __restrict__ avail, const unsigned int* __restrict__ mask_w,
             const float* __restrict__ bias, float* __restrict__ out) {
    extern __shared__ char dyn_raw[];
    __shared__ __align__(16) unsigned long long s_pm[PPAD];
    __shared__ __align__(16) unsigned long long s_bits[64];
    __shared__ __align__(16) unsigned long long s_avr[FF];
    __shared__ __align__(16) float s_scale[64];
    __shared__ __align__(16) float s_bias[HH];
    __shared__ unsigned char s_av[FF * FF];
    __shared__ unsigned int s_w[25];
    __shared__ int s_wp[26];
    __shared__ int s_P;
    __shared__ int s_rb[16];
    __shared__ __align__(8) unsigned long long s_mbar[2];

    uint32_t raw = smem_u32(dyn_raw);
    uint32_t base = (raw + 127u) & ~127u;
    char* dynp = dyn_raw + (base - raw);

    const int t = threadIdx.x;
    const int lane = t & 31, wid = t >> 5;
    const int m0 = blockIdx.x * 64;
    const uint32_t mbar0 = smem_u32(&s_mbar[0]);

    // ================= phase 0: tables (all in-CTA, parallel) =================
    if (t == 0) { MBARRIER_INIT(mbar0, 1); MBARRIER_INIT(mbar0 + 8, 1); }
    if (t < HH) s_bias[t] = bias[t];

    // avail dtype + bytes
    int okA = 1;
    for (int i = t; i < 400; i += 256) {
        unsigned int v = ((const unsigned int*)avail)[i];
        okA &= (v == 0u) | (v == 1u) | (v == 0x3F800000u);
    }
    okA = __syncthreads_and(okA);
    if (okA) { for (int i = t; i < FF * FF; i += 256) s_av[i] = ((const unsigned int*)avail)[i] != 0u; }
    else     { for (int i = t; i < FF * FF; i += 256) s_av[i] = ((const unsigned char*)avail)[i] != 0; }
    __syncthreads();

    if (t < FF) {
        unsigned long long r = 0ull;
        for (int j = t + 1; j < FF; ++j)
            if (s_av[t * FF + j]) r |= 1ull << j;
        s_avr[t] = r;
    }

    // pair flags -> ballots -> compacted s_pm
    int flg[4], pii[4], pjj[4];
    #pragma unroll
    for (int r = 0; r < 4; ++r) {
        int L = r * 256 + t;
        int f = 0, i = 0, j = 0;
        if (L < MAXP) { pair_decode(L, i, j); f = s_av[i * FF + j]; }
        flg[r] = f; pii[r] = i; pjj[r] = j;
        unsigned int bal = __ballot_sync(0xffffffffu, f);
        if ((t & 31) == 0) {
            int wi = r * 8 + (t >> 5);
            if (wi < 25) s_w[wi] = bal;
        }
    }
    __syncthreads();
    if (t == 0) {
        int s = 0;
        for (int w = 0; w < 25; ++w) { s_wp[w] = s; s += __popc(s_w[w]); }
        s_wp[25] = s; s_P = s;
    }
    __syncthreads();
    const int P = s_P;
    int nch = (P + KC - 1) / KC; if (nch < 1) nch = 1;
    const int plim = nch * 64;
    #pragma unroll
    for (int r = 0; r < 4; ++r) {
        int L = r * 256 + t;
        if (L < MAXP && flg[r]) {
            int wi = L >> 5;
            int pos = s_wp[wi] + __popc(s_w[wi] & ((1u << (L & 31)) - 1u));
            s_pm[pos] = (1ull << pii[r]) | (1ull << pjj[r]);
        }
    }
    for (int idx = t; idx < PPAD; idx += 256)
        if (idx >= P) s_pm[idx] = ~0ull;

    // own 64 mask rows -> bits + scale (coalesced stage in dyn)
    int okM;
    {
        unsigned int v0 = mask_w[t], v1 = mask_w[t + 256];
        int ok = ((v0 == 0u) | (v0 == 1u) | (v0 == 0x3F800000u)) &
                 ((v1 == 0u) | (v1 == 1u) | (v1 == 0x3F800000u));
        okM = __syncthreads_and(ok);
    }
    {
        unsigned int* stage = (unsigned int*)dynp;
        if (okM) { for (int idx = t; idx < 2560; idx += 256) stage[idx] = mask_w[(size_t)m0 * 40 + idx]; }
        else     { for (int idx = t; idx < 640; idx += 256) stage[idx] = mask_w[(size_t)m0 * 10 + idx]; }
        __syncthreads();
        if (t < 64) {
            unsigned long long b = 0ull;
            if (okM) {
                const unsigned int* rp = stage + t * 40;
                #pragma unroll
                for (int f = 0; f < FF; ++f) if (rp[f]) b |= 1ull << f;
            } else {
                const unsigned int* rp = stage + t * 10;
                #pragma unroll
                for (int wi = 0; wi < 10; ++wi) {
                    unsigned int w = rp[wi];
                    #pragma unroll
                    for (int by = 0; by < 4; ++by)
                        if ((w >> (by * 8)) & 0xFFu) b |= 1ull << (wi * 4 + by);
                }
            }
            s_bits[t] = b;
            int cnt = 0;
            unsigned long long x = b;
            while (x) {
                int i = __ffsll((long long)x) - 1;
                x &= x - 1;
                cnt += __popcll(s_avr[i] & b);
            }
            s_scale[t] = (cnt > 0) ? (1.0f / (float)cnt) : 0.0f;
        }
    }

    // ================= phase 1: EW tiles 16p x 32h =================
    {
        float* sE = (float*)dynp;                 // [16][36]
        float* sW = (float*)(dynp + 16 * 36 * 4); // [32][36]
        const int pcount = plim / 16;
        const int pg = t >> 5;        // 0..7 -> rows 2pg, 2pg+1
        const int hcol = t & 31;

        for (int T = blockIdx.x; T < pcount * 8; T += NCTA) {
            int p0 = (T >> 3) * 16, h0 = (T & 7) * 32;
            __syncthreads();          // smem free from previous use
            bool pad = (p0 >= P);
            if (t < 16) {
                int p = p0 + t;
                int rb = -1;
                if (!pad && p < P) {
                    int w = 0;
                    while (s_wp[w + 1] <= p) ++w;
                    unsigned int word = s_w[w];
                    int rem = p - s_wp[w];
                    for (int q = 0; q < rem; ++q) word &= word - 1;
                    int L = w * 32 + (__ffs(word) - 1);
                    int i, j; pair_decode(L, i, j);
                    rb = (i * FF + j) * DD;
                }
                s_rb[t] = rb;
            }
            __syncthreads();
            if (pad) {
                g_EWT[ewt_off(h0 + hcol, p0 + 2 * pg)]     = __float2half_rn(0.f);
                g_EWT[ewt_off(h0 + hcol, p0 + 2 * pg + 1)] = __float2half_rn(0.f);
                continue;
            }

            float4 re = make_float4(0.f, 0.f, 0.f, 0.f), rw;
            int erow = t >> 3, ekq = t & 7;       // E: t<128; W: all 256
            int wrow = t >> 3, wkq = t & 7;       // 32 rows x 8 kq
            if (t < 128) {
                int b = s_rb[erow];
                if (b >= 0) re = *(const float4*)(E + b + ekq * 4);
            }
            rw = *(const float4*)(W + (size_t)(h0 + wrow) * DD + wkq * 4);

            float a0 = 0.f, a1 = 0.f;
            for (int c = 0; c < DD / 32; ++c) {
                __syncthreads();
                if (t < 128) *(float4*)&sE[erow * 36 + ekq * 4] = re;
                *(float4*)&sW[wrow * 36 + wkq * 4] = rw;
                __syncthreads();
                if (c + 1 < DD / 32) {
                    int k0 = (c + 1) * 32;
                    if (t < 128) {
                        int b = s_rb[erow];
                        re = make_float4(0.f, 0.f, 0.f, 0.f);
                        if (b >= 0) re = *(const float4*)(E + b + k0 + ekq * 4);
                    }
                    rw = *(const float4*)(W + (size_t)(h0 + wrow) * DD + k0 + wkq * 4);
                }
                #pragma unroll
                for (int kk = 0; kk < 32; kk += 4) {
                    float4 e0 = *(float4*)&sE[(2 * pg) * 36 + kk];
                    float4 e1 = *(float4*)&sE[(2 * pg + 1) * 36 + kk];
                    float4 w0 = *(float4*)&sW[hcol * 36 + kk];
                    a0 += e0.x * w0.x + e0.y * w0.y + e0.z * w0.z + e0.w * w0.w;
                    a1 += e1.x * w0.x + e1.y * w0.y + e1.z * w0.z + e1.w * w0.w;
                }
            }
            g_EWT[ewt_off(h0 + hcol, p0 + 2 * pg)]     = __float2half_rn(a0);
            g_EWT[ewt_off(h0 + hcol, p0 + 2 * pg + 1)] = __float2half_rn(a1);
        }
    }

    // ================= grid barrier (monotonic counter, capture-safe) =========
    __threadfence();
    __syncthreads();
    if (t == 0) {
        unsigned int old = atomicAdd(&g_bar, 1u);
        unsigned int epoch = old & ~255u;
        volatile unsigned int* vb = &g_bar;
        while ((*vb - epoch) < 256u) { }
        __threadfence();
    }
    __syncthreads();

    // ================= phase 2: mma.sync GEMM =================
    const int wm = (wid & 1) * 32;
    const int wn = (wid >> 1) * 64;

    #define ISSUE_BULK(c, b) do {                                                  \
        if (t == 0) {                                                              \
            uint32_t mb = mbar0 + (b) * 8;                                         \
            MBARRIER_EXPECT_TX(mb, 32768u);                                        \
            uint32_t dst = base + (b) * BUFB + ABYTES;                             \
            const char* src = (const char*)g_EWT + (size_t)(c) * 32768;            \
            CP_BULK(dst, src, 16384u, mb);                                         \
            CP_BULK(dst + 16384u, src + 16384, 16384u, mb);                        \
        }                                                                          \
    } while (0)

    #define BUILD_A(c, bufbase) do {                                               \
        _Pragma("unroll")                                                          \
        for (int r = 0; r < 2; ++r) {                                              \
            int idx = t + r * 256;                                                 \
            int m = idx >> 3, kc = idx & 7;                                        \
            unsigned long long bb = s_bits[m];                                     \
            int pb = (c) * KC + kc * 8;                                            \
            unsigned long long q0 = s_pm[pb+0], q1 = s_pm[pb+1];                   \
            unsigned long long q2 = s_pm[pb+2], q3 = s_pm[pb+3];                   \
            unsigned long long q4 = s_pm[pb+4], q5 = s_pm[pb+5];                   \
            unsigned long long q6 = s_pm[pb+6], q7 = s_pm[pb+7];                   \
            uint32_t w0 = (((bb & q0) == q0) ? 0x3C00u : 0u) |                     \
                          (((bb & q1) == q1) ? 0x3C000000u : 0u);                  \
            uint32_t w1 = (((bb & q2) == q2) ? 0x3C00u : 0u) |                     \
                          (((bb & q3) == q3) ? 0x3C000000u : 0u);                  \
            uint32_t w2 = (((bb & q4) == q4) ? 0x3C00u : 0u) |                     \
                          (((bb & q5) == q5) ? 0x3C000000u : 0u);                  \
            uint32_t w3 = (((bb & q6) == q6) ? 0x3C00u : 0u) |                     \
                          (((bb & q7) == q7) ? 0x3C000000u : 0u);                  \
            uint32_t dst = (bufbase) + m * 128 + ((kc ^ (m & 7)) << 4);            \
            asm volatile("st.shared.v4.b32 [%0], {%1,%2,%3,%4};"                   \
                         :: "r"(dst), "r"(w0), "r"(w1), "r"(w2), "r"(w3));         \
        }                                                                          \
    } while (0)

    ISSUE_BULK(0, 0);
    BUILD_A(0, base);
    __syncthreads();

    float acc[2][8][4];
    #pragma unroll
    for (int i = 0; i < 2; ++i)
        #pragma unroll
        for (int j = 0; j < 8; ++j)
            #pragma unroll
            for (int q = 0; q < 4; ++q) acc[i][j][q] = 0.f;

    for (int c = 0; c < nch; ++c) {
        int b = c & 1;
        uint32_t cur = base + b * BUFB;
        if (c + 1 < nch) {
            ISSUE_BULK(c + 1, (c + 1) & 1);
            BUILD_A(c + 1, base + ((c + 1) & 1) * BUFB);
        }
        MBARRIER_WAIT_PARITY(mbar0 + b * 8, (c >> 1) & 1);

        uint32_t Ab = cur, Bb = cur + ABYTES;
        #pragma unroll
        for (int ks = 0; ks < 4; ++ks) {
            uint32_t a[2][4];
            #pragma unroll
            for (int mi = 0; mi < 2; ++mi) {
                int arow = wm + mi * 16 + (lane & 7) + ((lane >> 3) & 1) * 8;
                int akc = ks * 2 + (lane >> 4);
                uint32_t ad = Ab + arow * 128 + ((akc ^ (arow & 7)) << 4);
                LDSM4(a[mi][0], a[mi][1], a[mi][2], a[mi][3], ad);
            }
            #pragma unroll
            for (int nb2 = 0; nb2 < 4; ++nb2) {
                int brow = wn + nb2 * 16 + (lane & 7) + (lane >> 4) * 8;
                int bkc = ks * 2 + ((lane >> 3) & 1);
                uint32_t off = brow * 128 + ((bkc ^ (brow & 7)) << 4);
                uint32_t b0, b1, b2, b3;
                LDSM4(b0, b1, b2, b3, Bb + off);
                #pragma unroll
                for (int mi = 0; mi < 2; ++mi) {
                    MMA_F16(acc[mi][nb2 * 2 + 0], a[mi], b0, b1);
                    MMA_F16(acc[mi][nb2 * 2 + 1], a[mi], b2, b3);
                }
            }
        }
        __syncthreads();   // delimit buffer reuse; makes BUILD_A(c+1) visible
    }

    // epilogue: scale by 1/cnt, add bias, store
    #pragma unroll
    for (int mi = 0; mi < 2; ++mi) {
        int rl = wm + mi * 16 + (lane >> 2);
        int row0 = m0 + rl;
        float sc0 = s_scale[rl];
        float sc1 = s_scale[rl + 8];
        #pragma unroll
        for (int nf = 0; nf < 8; ++nf) {
            int col = wn + (nf >> 1) * 16 + (nf & 1) * 8 + 2 * (lane & 3);
            float bv0 = s_bias[col], bv1 = s_bias[col + 1];
            float2 o0, o1;
            o0.x = acc[mi][nf][0] * sc0 + bv0;
            o0.y = acc[mi][nf][1] * sc0 + bv1;
            o1.x = acc[mi][nf][2] * sc1 + bv0;
            o1.y = acc[mi][nf][3] * sc1 + bv1;
            *(float2*)(out + (size_t)row0 * HH + col) = o0;
            *(float2*)(out + (size_t)(row0 + 8) * HH + col) = o1;
        }
    }
}

// ---------------- launch ----------------
extern "C" void kernel_launch(void* const* d_in, const int* in_sizes, int n_in,
                              void* d_out, int out_size) {
    const void* mask = d_in[0];                    // [64,256,40] bool
    const float* E = (const float*)d_in[1];        // [40,40,768] f32
    const void* avail = (const void*)d_in[2];      // [40,40] bool
    const float* W = (const float*)d_in[3];        // [256,768] f32
    const float* bias = (const float*)d_in[4];     // [256] f32
    float* out = (float*)d_out;                    // [64,256,256] f32

    cudaFuncSetAttribute(fused_kernel, cudaFuncAttributeMaxDynamicSharedMemorySize,
                         DSMEM_BYTES);

    fused_kernel<<<NCTA, 256, DSMEM_BYTES>>>(E, W, avail,
                                             (const unsigned int*)mask, bias, out);
}